// round 1
// baseline (speedup 1.0000x reference)
#include <cuda_runtime.h>

#define HID   1024
#define NHEAD 16
#define HDIM  64
#define BATCH 2
#define SEQ   2048
#define MROWS (BATCH*SEQ)   // 4096
#define N3    (3*HID)       // 3072

// Scratch (allocation-free rule: __device__ globals)
__device__ float g_xln [(size_t)MROWS * HID];   // 16.8 MB
__device__ float g_qkv [(size_t)MROWS * N3];    // 50.3 MB
__device__ float g_attn[(size_t)MROWS * HID];   // 16.8 MB

// ---------------------------------------------------------------------------
// LayerNorm: one block per row, 256 threads, float4 per thread.
// ---------------------------------------------------------------------------
__global__ void ln_kernel(const float* __restrict__ x,
                          const float* __restrict__ gamma,
                          const float* __restrict__ beta,
                          float* __restrict__ out) {
    int row = blockIdx.x;
    int t = threadIdx.x;            // 256 threads, HID/4 = 256 float4s
    const float4 v = reinterpret_cast<const float4*>(x)[(size_t)row * (HID/4) + t];
    float s  = v.x + v.y + v.z + v.w;
    float sq = v.x*v.x + v.y*v.y + v.z*v.z + v.w*v.w;
    #pragma unroll
    for (int o = 16; o > 0; o >>= 1) {
        s  += __shfl_xor_sync(0xffffffffu, s,  o);
        sq += __shfl_xor_sync(0xffffffffu, sq, o);
    }
    __shared__ float rs[8], rq[8];
    int warp = t >> 5, lane = t & 31;
    if (lane == 0) { rs[warp] = s; rq[warp] = sq; }
    __syncthreads();
    s = 0.f; sq = 0.f;
    #pragma unroll
    for (int i = 0; i < 8; i++) { s += rs[i]; sq += rq[i]; }
    float mu   = s * (1.0f / HID);
    float var  = fmaxf(sq * (1.0f / HID) - mu * mu, 0.0f);
    float rstd = rsqrtf(var + 1e-12f);
    const float4 g4 = reinterpret_cast<const float4*>(gamma)[t];
    const float4 b4 = reinterpret_cast<const float4*>(beta)[t];
    float4 o;
    o.x = (v.x - mu) * rstd * g4.x + b4.x;
    o.y = (v.y - mu) * rstd * g4.y + b4.y;
    o.z = (v.z - mu) * rstd * g4.z + b4.z;
    o.w = (v.w - mu) * rstd * g4.w + b4.w;
    reinterpret_cast<float4*>(out)[(size_t)row * (HID/4) + t] = o;
}

// ---------------------------------------------------------------------------
// Tiled SGEMM: C[M,N] = A[M,1024] @ B[1024,N] (+epilogue).
// 128x128 tile, BK=8, 256 threads, 8x8 per thread.
// EPI=0: += bias; scale K columns [1024,2048) by 1/8 (rescaled-key trick)
// EPI=1: += bias + residual
// ---------------------------------------------------------------------------
template<int EPI>
__global__ void __launch_bounds__(256, 2) sgemm_kernel(
        const float* __restrict__ A, const float* __restrict__ Bw,
        const float* __restrict__ bias, const float* __restrict__ resid,
        float* __restrict__ C, int N) {
    __shared__ float As[8 * 128];   // As[k][m]
    __shared__ float Bs[8 * 128];   // Bs[k][n]
    int tid = threadIdx.x;
    int tx = tid & 15, ty = tid >> 4;
    int r0 = blockIdx.y * 128;
    int c0 = blockIdx.x * 128;

    int arow = tid >> 1;           // 0..127
    int acol = (tid & 1) * 4;      // 0 or 4
    int brow = tid >> 5;           // 0..7
    int bcol = (tid & 31) * 4;     // 0..124

    float acc[8][8];
    #pragma unroll
    for (int i = 0; i < 8; i++)
        #pragma unroll
        for (int j = 0; j < 8; j++) acc[i][j] = 0.f;

    const float* Aptr = A  + (size_t)(r0 + arow) * HID + acol;
    const float* Bptr = Bw + (size_t)brow * N + c0 + bcol;

    for (int k0 = 0; k0 < HID; k0 += 8) {
        float4 av = *reinterpret_cast<const float4*>(Aptr + k0);
        float4 bv = *reinterpret_cast<const float4*>(Bptr + (size_t)k0 * N);
        As[(acol + 0) * 128 + arow] = av.x;
        As[(acol + 1) * 128 + arow] = av.y;
        As[(acol + 2) * 128 + arow] = av.z;
        As[(acol + 3) * 128 + arow] = av.w;
        *reinterpret_cast<float4*>(&Bs[brow * 128 + bcol]) = bv;
        __syncthreads();
        #pragma unroll
        for (int kk = 0; kk < 8; kk++) {
            float4 a[2], b[2];
            a[0] = *reinterpret_cast<const float4*>(&As[kk * 128 + ty * 8]);
            a[1] = *reinterpret_cast<const float4*>(&As[kk * 128 + ty * 8 + 4]);
            b[0] = *reinterpret_cast<const float4*>(&Bs[kk * 128 + tx * 8]);
            b[1] = *reinterpret_cast<const float4*>(&Bs[kk * 128 + tx * 8 + 4]);
            const float* af = reinterpret_cast<const float*>(a);
            const float* bf = reinterpret_cast<const float*>(b);
            #pragma unroll
            for (int i = 0; i < 8; i++)
                #pragma unroll
                for (int j = 0; j < 8; j++)
                    acc[i][j] = fmaf(af[i], bf[j], acc[i][j]);
        }
        __syncthreads();
    }

    #pragma unroll
    for (int i = 0; i < 8; i++) {
        int row = r0 + ty * 8 + i;
        #pragma unroll
        for (int j = 0; j < 8; j++) {
            int col = c0 + tx * 8 + j;
            float cv = acc[i][j] + bias[col];
            if (EPI == 0) {
                if (col >= HID && col < 2 * HID) cv *= 0.125f;  // pre-scale K
            } else {
                cv += resid[(size_t)row * HID + col];
            }
            C[(size_t)row * N + col] = cv;
        }
    }
}

// ---------------------------------------------------------------------------
// Flash attention: one block per (q-tile of 64, head, batch). 256 threads.
// smem: QsT[d][m], KsT[d][n], Vs[k][d], PsT[k][m] each [64][68] fp32.
// Thread (ty,tx) owns a 4x4 micro-tile; rows = ty*4.., cols = tx*4..
// ---------------------------------------------------------------------------
#define PAD 68
#define ATTN_SMEM (4 * 64 * PAD * 4)

__global__ void __launch_bounds__(256, 2) attn_kernel(
        const float* __restrict__ qkv,
        const float* __restrict__ mask,
        float* __restrict__ attn_out) {
    extern __shared__ float sm[];
    float* QsT = sm;              // [64][PAD]  QsT[d*PAD + m]
    float* KsT = QsT + 64 * PAD;  // [64][PAD]  KsT[d*PAD + n]
    float* Vs  = KsT + 64 * PAD;  // [64][PAD]  Vs [k*PAD + d]
    float* PsT = Vs  + 64 * PAD;  // [64][PAD]  PsT[k*PAD + m]

    int tid = threadIdx.x;
    int tx = tid & 15, ty = tid >> 4;
    int tx4 = tx * 4, ty4 = ty * 4;
    int q0 = blockIdx.x * 64;
    int h  = blockIdx.y;
    int b  = blockIdx.z;

    const float* qbase = qkv + (size_t)(b * SEQ + q0) * N3 + h * HDIM;
    const float* kbase = qkv + (size_t)b * SEQ * N3 + HID     + h * HDIM;
    const float* vbase = qkv + (size_t)b * SEQ * N3 + 2 * HID + h * HDIM;
    const float* mbase = mask + (size_t)b * SEQ * SEQ;

    // Load Q tile transposed
    #pragma unroll
    for (int it = 0; it < 4; it++) {
        int lin = it * 1024 + tid * 4;
        int r = lin >> 6, d0 = lin & 63;
        float4 v = *reinterpret_cast<const float4*>(qbase + (size_t)r * N3 + d0);
        QsT[(d0 + 0) * PAD + r] = v.x;
        QsT[(d0 + 1) * PAD + r] = v.y;
        QsT[(d0 + 2) * PAD + r] = v.z;
        QsT[(d0 + 3) * PAD + r] = v.w;
    }

    float mstate[4], lstate[4], acc[4][4];
    #pragma unroll
    for (int i = 0; i < 4; i++) {
        mstate[i] = -1e30f; lstate[i] = 0.f;
        #pragma unroll
        for (int j = 0; j < 4; j++) acc[i][j] = 0.f;
    }

    for (int k0 = 0; k0 < SEQ; k0 += 64) {
        __syncthreads();   // previous PV done before overwriting K/V
        #pragma unroll
        for (int it = 0; it < 4; it++) {
            int lin = it * 1024 + tid * 4;
            int r = lin >> 6, d0 = lin & 63;
            float4 kv = *reinterpret_cast<const float4*>(kbase + (size_t)(k0 + r) * N3 + d0);
            KsT[(d0 + 0) * PAD + r] = kv.x;
            KsT[(d0 + 1) * PAD + r] = kv.y;
            KsT[(d0 + 2) * PAD + r] = kv.z;
            KsT[(d0 + 3) * PAD + r] = kv.w;
            float4 vv = *reinterpret_cast<const float4*>(vbase + (size_t)(k0 + r) * N3 + d0);
            *reinterpret_cast<float4*>(&Vs[r * PAD + d0]) = vv;
        }
        __syncthreads();

        // S = Q @ K^T  (64x64x64)
        float sc[4][4];
        #pragma unroll
        for (int i = 0; i < 4; i++)
            #pragma unroll
            for (int j = 0; j < 4; j++) sc[i][j] = 0.f;
        #pragma unroll 16
        for (int d = 0; d < 64; d++) {
            float4 a  = *reinterpret_cast<const float4*>(&QsT[d * PAD + ty4]);
            float4 kb = *reinterpret_cast<const float4*>(&KsT[d * PAD + tx4]);
            const float* af = reinterpret_cast<const float*>(&a);
            const float* bf = reinterpret_cast<const float*>(&kb);
            #pragma unroll
            for (int i = 0; i < 4; i++)
                #pragma unroll
                for (int j = 0; j < 4; j++)
                    sc[i][j] = fmaf(af[i], bf[j], sc[i][j]);
        }
        // + attention mask
        #pragma unroll
        for (int i = 0; i < 4; i++) {
            float4 mv = *reinterpret_cast<const float4*>(
                &mbase[(size_t)(q0 + ty4 + i) * SEQ + k0 + tx4]);
            sc[i][0] += mv.x; sc[i][1] += mv.y; sc[i][2] += mv.z; sc[i][3] += mv.w;
        }
        // online softmax (row stats reduced across the 16 tx-lanes)
        #pragma unroll
        for (int i = 0; i < 4; i++) {
            float rm = fmaxf(fmaxf(sc[i][0], sc[i][1]), fmaxf(sc[i][2], sc[i][3]));
            #pragma unroll
            for (int o = 8; o > 0; o >>= 1)
                rm = fmaxf(rm, __shfl_xor_sync(0xffffffffu, rm, o));
            float mnew = fmaxf(mstate[i], rm);
            float corr = __expf(mstate[i] - mnew);
            float rsum = 0.f;
            #pragma unroll
            for (int j = 0; j < 4; j++) {
                float p = __expf(sc[i][j] - mnew);
                rsum += p;
                PsT[(tx4 + j) * PAD + ty4 + i] = p;
            }
            #pragma unroll
            for (int o = 8; o > 0; o >>= 1)
                rsum += __shfl_xor_sync(0xffffffffu, rsum, o);
            lstate[i] = lstate[i] * corr + rsum;
            mstate[i] = mnew;
            #pragma unroll
            for (int j = 0; j < 4; j++) acc[i][j] *= corr;
        }
        __syncthreads();   // PsT visible

        // acc += P @ V  (64x64x64)
        #pragma unroll 16
        for (int k = 0; k < 64; k++) {
            float4 p  = *reinterpret_cast<const float4*>(&PsT[k * PAD + ty4]);
            float4 vv = *reinterpret_cast<const float4*>(&Vs[k * PAD + tx4]);
            const float* pf = reinterpret_cast<const float*>(&p);
            const float* vf = reinterpret_cast<const float*>(&vv);
            #pragma unroll
            for (int i = 0; i < 4; i++)
                #pragma unroll
                for (int j = 0; j < 4; j++)
                    acc[i][j] = fmaf(pf[i], vf[j], acc[i][j]);
        }
    }

    #pragma unroll
    for (int i = 0; i < 4; i++) {
        float inv = 1.0f / lstate[i];
        float4 o;
        o.x = acc[i][0] * inv; o.y = acc[i][1] * inv;
        o.z = acc[i][2] * inv; o.w = acc[i][3] * inv;
        *reinterpret_cast<float4*>(
            &attn_out[(size_t)(b * SEQ + q0 + ty4 + i) * HID + h * HDIM + tx4]) = o;
    }
}

// ---------------------------------------------------------------------------
extern "C" void kernel_launch(void* const* d_in, const int* in_sizes, int n_in,
                              void* d_out, int out_size) {
    const float* hidden = (const float*)d_in[0];
    const float* mask   = (const float*)d_in[1];
    const float* w_qkv  = (const float*)d_in[2];
    const float* b_qkv  = (const float*)d_in[3];
    const float* w_out  = (const float*)d_in[4];
    const float* b_out  = (const float*)d_in[5];
    const float* ln_g   = (const float*)d_in[6];
    const float* ln_b   = (const float*)d_in[7];
    float* out = (float*)d_out;

    float *xln, *qkv, *attn;
    cudaGetSymbolAddress((void**)&xln,  g_xln);
    cudaGetSymbolAddress((void**)&qkv,  g_qkv);
    cudaGetSymbolAddress((void**)&attn, g_attn);

    // 1) LayerNorm
    ln_kernel<<<MROWS, 256>>>(hidden, ln_g, ln_b, xln);

    // 2) QKV projection (+bias, K pre-scale by 1/8)
    dim3 g1(N3 / 128, MROWS / 128);
    sgemm_kernel<0><<<g1, 256>>>(xln, w_qkv, b_qkv, nullptr, qkv, N3);

    // 3) Flash attention
    cudaFuncSetAttribute(attn_kernel,
                         cudaFuncAttributeMaxDynamicSharedMemorySize, ATTN_SMEM);
    dim3 g2(SEQ / 64, NHEAD, BATCH);
    attn_kernel<<<g2, 256, ATTN_SMEM>>>(qkv, mask, attn);

    // 4) Output projection + bias + residual
    dim3 g3(HID / 128, MROWS / 128);
    sgemm_kernel<1><<<g3, 256>>>(attn, w_out, b_out, hidden, out, HID);
}

// round 4
// speedup vs baseline: 2.4993x; 2.4993x over previous
#include <cuda_runtime.h>

#define HID   1024
#define NHEAD 16
#define HDIM  64
#define BATCH 2
#define SEQ   2048
#define MROWS (BATCH*SEQ)   // 4096
#define N3    (3*HID)       // 3072

// Scratch (allocation-free rule: __device__ globals)
__device__ float g_xln [(size_t)MROWS * HID];
__device__ float g_qkv [(size_t)MROWS * N3];
__device__ float g_attn[(size_t)MROWS * HID];

// ---------------------------------------------------------------------------
// helpers
// ---------------------------------------------------------------------------
__device__ __forceinline__ void mma8(float* d, const unsigned* a, const unsigned* b) {
    asm volatile("mma.sync.aligned.m16n8k8.row.col.f32.tf32.tf32.f32 "
        "{%0,%1,%2,%3}, {%4,%5,%6,%7}, {%8,%9}, {%0,%1,%2,%3};\n"
        : "+f"(d[0]), "+f"(d[1]), "+f"(d[2]), "+f"(d[3])
        : "r"(a[0]), "r"(a[1]), "r"(a[2]), "r"(a[3]), "r"(b[0]), "r"(b[1]));
}

__device__ __forceinline__ void cpa16(float* s, const float* g) {
    unsigned sa = (unsigned)__cvta_generic_to_shared(s);
    asm volatile("cp.async.cg.shared.global [%0], [%1], 16;\n" :: "r"(sa), "l"(g));
}
#define CP_COMMIT()  asm volatile("cp.async.commit_group;\n")
#define CP_WAIT(n)   asm volatile("cp.async.wait_group %0;\n" :: "n"(n))

// ---------------------------------------------------------------------------
// LayerNorm: one block per row, 256 threads, float4 per thread.
// ---------------------------------------------------------------------------
__global__ void ln_kernel(const float* __restrict__ x,
                          const float* __restrict__ gamma,
                          const float* __restrict__ beta,
                          float* __restrict__ out) {
    int row = blockIdx.x;
    int t = threadIdx.x;
    const float4 v = reinterpret_cast<const float4*>(x)[(size_t)row * (HID/4) + t];
    float s  = v.x + v.y + v.z + v.w;
    float sq = v.x*v.x + v.y*v.y + v.z*v.z + v.w*v.w;
    #pragma unroll
    for (int o = 16; o > 0; o >>= 1) {
        s  += __shfl_xor_sync(0xffffffffu, s,  o);
        sq += __shfl_xor_sync(0xffffffffu, sq, o);
    }
    __shared__ float rs[8], rq[8];
    int warp = t >> 5, lane = t & 31;
    if (lane == 0) { rs[warp] = s; rq[warp] = sq; }
    __syncthreads();
    s = 0.f; sq = 0.f;
    #pragma unroll
    for (int i = 0; i < 8; i++) { s += rs[i]; sq += rq[i]; }
    float mu   = s * (1.0f / HID);
    float var  = fmaxf(sq * (1.0f / HID) - mu * mu, 0.0f);
    float rstd = rsqrtf(var + 1e-12f);
    const float4 g4 = reinterpret_cast<const float4*>(gamma)[t];
    const float4 b4 = reinterpret_cast<const float4*>(beta)[t];
    float4 o;
    o.x = (v.x - mu) * rstd * g4.x + b4.x;
    o.y = (v.y - mu) * rstd * g4.y + b4.y;
    o.z = (v.z - mu) * rstd * g4.z + b4.z;
    o.w = (v.w - mu) * rstd * g4.w + b4.w;
    reinterpret_cast<float4*>(out)[(size_t)row * (HID/4) + t] = o;
}

// ---------------------------------------------------------------------------
// TF32 tensor-core GEMM: C[M,N] = A[M,1024] @ B[1024,N] (+epilogue)
// 128x128 block tile, BK=16, 256 threads (8 warps, 4x2 grid of 32x64 tiles).
// cp.async double-buffered.  EPI=0: +bias, scale cols[1024,2048) by 1/8.
// EPI=1: +bias +residual.
// ---------------------------------------------------------------------------
#define AST 20    // A smem stride (== 4*odd mod 32 -> conflict-free A frags)
#define BST 136   // B smem stride (== 8*odd mod 32 -> conflict-free B frags)

template<int EPI>
__global__ void __launch_bounds__(256) mm_tf32(
        const float* __restrict__ A, const float* __restrict__ B,
        const float* __restrict__ bias, const float* __restrict__ resid,
        float* __restrict__ C, int N) {
    __shared__ __align__(16) float As[2][128 * AST];
    __shared__ __align__(16) float Bs[2][16 * BST];
    int tid = threadIdx.x;
    int r0 = blockIdx.y * 128, c0 = blockIdx.x * 128;
    int warp = tid >> 5, lane = tid & 31;
    int g = lane >> 2, q = lane & 3;
    int wm = (warp & 3) * 32, wn = (warp >> 2) * 64;

    float acc[2][8][4] = {};

    auto issue = [&](int k0, int st) {
        #pragma unroll
        for (int p = 0; p < 2; p++) {
            int fi = tid + p * 256;            // 512 float4s of A (128x16)
            int row = fi >> 2, c4 = (fi & 3) * 4;
            cpa16(&As[st][row * AST + c4], &A[(size_t)(r0 + row) * HID + k0 + c4]);
        }
        #pragma unroll
        for (int p = 0; p < 2; p++) {
            int fi = tid + p * 256;            // 512 float4s of B (16x128)
            int row = fi >> 5, c4 = (fi & 31) * 4;
            cpa16(&Bs[st][row * BST + c4], &B[(size_t)(k0 + row) * N + c0 + c4]);
        }
    };

    issue(0, 0); CP_COMMIT();
    for (int it = 0; it < 64; it++) {
        if (it < 63) { issue((it + 1) * 16, (it + 1) & 1); CP_COMMIT(); CP_WAIT(1); }
        else CP_WAIT(0);
        __syncthreads();
        const float* as = As[it & 1];
        const float* bs = Bs[it & 1];
        #pragma unroll
        for (int ks = 0; ks < 16; ks += 8) {
            unsigned a[2][4], b[8][2];
            #pragma unroll
            for (int i = 0; i < 2; i++) {
                int r = wm + i * 16;
                a[i][0] = __float_as_uint(as[(r + g    ) * AST + ks + q    ]);
                a[i][1] = __float_as_uint(as[(r + g + 8) * AST + ks + q    ]);
                a[i][2] = __float_as_uint(as[(r + g    ) * AST + ks + q + 4]);
                a[i][3] = __float_as_uint(as[(r + g + 8) * AST + ks + q + 4]);
            }
            #pragma unroll
            for (int j = 0; j < 8; j++) {
                int cn = wn + j * 8;
                b[j][0] = __float_as_uint(bs[(ks + q    ) * BST + cn + g]);
                b[j][1] = __float_as_uint(bs[(ks + q + 4) * BST + cn + g]);
            }
            #pragma unroll
            for (int i = 0; i < 2; i++)
                #pragma unroll
                for (int j = 0; j < 8; j++)
                    mma8(acc[i][j], a[i], b[j]);
        }
        __syncthreads();
    }

    #pragma unroll
    for (int i = 0; i < 2; i++) {
        #pragma unroll
        for (int j = 0; j < 8; j++) {
            int col = c0 + wn + j * 8 + q * 2;
            float b0 = bias[col], b1 = bias[col + 1];
            #pragma unroll
            for (int hh = 0; hh < 2; hh++) {
                int row = r0 + wm + i * 16 + g + hh * 8;
                float v0 = acc[i][j][hh * 2 + 0] + b0;
                float v1 = acc[i][j][hh * 2 + 1] + b1;
                if (EPI == 0) {
                    if (col >= HID && col < 2 * HID) { v0 *= 0.125f; v1 *= 0.125f; }
                } else {
                    v0 += resid[(size_t)row * HID + col];
                    v1 += resid[(size_t)row * HID + col + 1];
                }
                *reinterpret_cast<float2*>(&C[(size_t)row * N + col]) = make_float2(v0, v1);
            }
        }
    }
}

// ---------------------------------------------------------------------------
// TF32 tensor-core flash attention.
// Block: 128 threads (4 warps), 128 q-rows (warp w owns rows w*32..w*32+31).
// K/V kept row-major [key][d] in smem (fragment indexing = implicit transpose),
// cp.async double-buffered 64-key tiles. P via smem.
// ---------------------------------------------------------------------------
#define QT 128
#define KT 64
#define QSS 68   // 4*odd mod 32 (A-frag reads)
#define KSS 68   // 4*odd mod 32 (B-frag reads addr = n*KSS + k)
#define VSS 72   // 8*odd mod 32 (B-frag reads addr = k*VSS + n)
#define PSS 68
#define ATTN_SMEM ((QT*QSS + QT*PSS + 2*KT*KSS + 2*KT*VSS) * 4)

__global__ void __launch_bounds__(128) attn_tf32(
        const float* __restrict__ qkv,
        const float* __restrict__ mask,
        float* __restrict__ out) {
    extern __shared__ __align__(16) float sm[];
    float* Qs = sm;                       // [128][QSS]
    float* Ps = Qs + QT * QSS;            // [128][PSS]
    float* Ks = Ps + QT * PSS;            // [2][64][KSS]
    float* Vs = Ks + 2 * KT * KSS;        // [2][64][VSS]

    int tid = threadIdx.x, warp = tid >> 5, lane = tid & 31;
    int g = lane >> 2, q = lane & 3;
    int q0 = blockIdx.x * QT;
    int h = blockIdx.y, b = blockIdx.z;
    int m0 = warp * 32;

    const float* qbase = qkv + (size_t)(b * SEQ + q0) * N3 + h * HDIM;
    const float* kbase = qkv + (size_t)b * SEQ * N3 + HID     + h * HDIM;
    const float* vbase = qkv + (size_t)b * SEQ * N3 + 2 * HID + h * HDIM;
    const float* mbase = mask + (size_t)b * SEQ * SEQ;

    // Load Q tile (128 x 64): 2048 float4 / 128 threads = 16 each
    #pragma unroll
    for (int p = 0; p < 16; p++) {
        int fi = tid + p * 128;
        int row = fi >> 4, c4 = (fi & 15) * 4;
        *reinterpret_cast<float4*>(&Qs[row * QSS + c4]) =
            *reinterpret_cast<const float4*>(&qbase[(size_t)row * N3 + c4]);
    }

    auto issue = [&](int kt, int st) {
        #pragma unroll
        for (int p = 0; p < 8; p++) {
            int fi = tid + p * 128;          // 1024 float4s each
            int row = fi >> 4, c4 = (fi & 15) * 4;
            cpa16(&Ks[st * KT * KSS + row * KSS + c4],
                  &kbase[(size_t)(kt * KT + row) * N3 + c4]);
            cpa16(&Vs[st * KT * VSS + row * VSS + c4],
                  &vbase[(size_t)(kt * KT + row) * N3 + c4]);
        }
    };

    float oacc[2][8][4] = {};
    float mst[2][2], lst[2][2];
    #pragma unroll
    for (int i = 0; i < 2; i++)
        #pragma unroll
        for (int hh = 0; hh < 2; hh++) { mst[i][hh] = -1e30f; lst[i][hh] = 0.f; }

    issue(0, 0); CP_COMMIT();
    for (int kt = 0; kt < SEQ / KT; kt++) {
        if (kt < SEQ / KT - 1) { issue(kt + 1, (kt + 1) & 1); CP_COMMIT(); CP_WAIT(1); }
        else CP_WAIT(0);
        __syncthreads();
        const float* ks = Ks + (kt & 1) * KT * KSS;
        const float* vs = Vs + (kt & 1) * KT * VSS;
        int k0 = kt * KT;

        // ---- S = Q @ K^T (32x64 per warp) ----
        float sacc[2][8][4] = {};
        #pragma unroll
        for (int kk = 0; kk < 8; kk++) {
            unsigned a[2][4], bf[8][2];
            #pragma unroll
            for (int i = 0; i < 2; i++) {
                int r = m0 + i * 16;
                a[i][0] = __float_as_uint(Qs[(r + g    ) * QSS + kk * 8 + q    ]);
                a[i][1] = __float_as_uint(Qs[(r + g + 8) * QSS + kk * 8 + q    ]);
                a[i][2] = __float_as_uint(Qs[(r + g    ) * QSS + kk * 8 + q + 4]);
                a[i][3] = __float_as_uint(Qs[(r + g + 8) * QSS + kk * 8 + q + 4]);
            }
            #pragma unroll
            for (int j = 0; j < 8; j++) {
                bf[j][0] = __float_as_uint(ks[(j * 8 + g) * KSS + kk * 8 + q    ]);
                bf[j][1] = __float_as_uint(ks[(j * 8 + g) * KSS + kk * 8 + q + 4]);
            }
            #pragma unroll
            for (int i = 0; i < 2; i++)
                #pragma unroll
                for (int j = 0; j < 8; j++)
                    mma8(sacc[i][j], a[i], bf[j]);
        }

        // ---- + mask ----
        #pragma unroll
        for (int i = 0; i < 2; i++) {
            int row0 = q0 + m0 + i * 16 + g;
            #pragma unroll
            for (int j = 0; j < 8; j++) {
                int colk = k0 + j * 8 + q * 2;
                float2 mv0 = *reinterpret_cast<const float2*>(&mbase[(size_t)row0 * SEQ + colk]);
                float2 mv1 = *reinterpret_cast<const float2*>(&mbase[(size_t)(row0 + 8) * SEQ + colk]);
                sacc[i][j][0] += mv0.x; sacc[i][j][1] += mv0.y;
                sacc[i][j][2] += mv1.x; sacc[i][j][3] += mv1.y;
            }
        }

        // ---- online softmax + P store ----
        #pragma unroll
        for (int i = 0; i < 2; i++) {
            #pragma unroll
            for (int hh = 0; hh < 2; hh++) {
                float rmax = -1e30f;
                #pragma unroll
                for (int j = 0; j < 8; j++)
                    rmax = fmaxf(rmax, fmaxf(sacc[i][j][hh*2], sacc[i][j][hh*2+1]));
                rmax = fmaxf(rmax, __shfl_xor_sync(0xffffffffu, rmax, 1));
                rmax = fmaxf(rmax, __shfl_xor_sync(0xffffffffu, rmax, 2));
                float mnew = fmaxf(mst[i][hh], rmax);
                float corr = __expf(mst[i][hh] - mnew);
                float rsum = 0.f;
                int prow = m0 + i * 16 + g + hh * 8;
                #pragma unroll
                for (int j = 0; j < 8; j++) {
                    float p0 = __expf(sacc[i][j][hh*2]   - mnew);
                    float p1 = __expf(sacc[i][j][hh*2+1] - mnew);
                    rsum += p0 + p1;
                    *reinterpret_cast<float2*>(&Ps[prow * PSS + j * 8 + q * 2]) =
                        make_float2(p0, p1);
                }
                rsum += __shfl_xor_sync(0xffffffffu, rsum, 1);
                rsum += __shfl_xor_sync(0xffffffffu, rsum, 2);
                lst[i][hh] = lst[i][hh] * corr + rsum;
                mst[i][hh] = mnew;
                #pragma unroll
                for (int j = 0; j < 8; j++) {
                    oacc[i][j][hh*2]   *= corr;
                    oacc[i][j][hh*2+1] *= corr;
                }
            }
        }
        __syncwarp();

        // ---- O += P @ V (32x64 per warp, k=64 keys) ----
        #pragma unroll
        for (int kk = 0; kk < 8; kk++) {
            unsigned a[2][4], bf[8][2];
            #pragma unroll
            for (int i = 0; i < 2; i++) {
                int r = m0 + i * 16;
                a[i][0] = __float_as_uint(Ps[(r + g    ) * PSS + kk * 8 + q    ]);
                a[i][1] = __float_as_uint(Ps[(r + g + 8) * PSS + kk * 8 + q    ]);
                a[i][2] = __float_as_uint(Ps[(r + g    ) * PSS + kk * 8 + q + 4]);
                a[i][3] = __float_as_uint(Ps[(r + g + 8) * PSS + kk * 8 + q + 4]);
            }
            #pragma unroll
            for (int j = 0; j < 8; j++) {
                bf[j][0] = __float_as_uint(vs[(kk * 8 + q    ) * VSS + j * 8 + g]);
                bf[j][1] = __float_as_uint(vs[(kk * 8 + q + 4) * VSS + j * 8 + g]);
            }
            #pragma unroll
            for (int i = 0; i < 2; i++)
                #pragma unroll
                for (int j = 0; j < 8; j++)
                    mma8(oacc[i][j], a[i], bf[j]);
        }
        __syncthreads();
    }

    // ---- normalize + write ----
    #pragma unroll
    for (int i = 0; i < 2; i++) {
        float inv0 = 1.0f / lst[i][0];
        float inv1 = 1.0f / lst[i][1];
        #pragma unroll
        for (int j = 0; j < 8; j++) {
            int col = h * HDIM + j * 8 + q * 2;
            int row0 = b * SEQ + q0 + m0 + i * 16 + g;
            *reinterpret_cast<float2*>(&out[(size_t)row0 * HID + col]) =
                make_float2(oacc[i][j][0] * inv0, oacc[i][j][1] * inv0);
            *reinterpret_cast<float2*>(&out[(size_t)(row0 + 8) * HID + col]) =
                make_float2(oacc[i][j][2] * inv1, oacc[i][j][3] * inv1);
        }
    }
}

// ---------------------------------------------------------------------------
extern "C" void kernel_launch(void* const* d_in, const int* in_sizes, int n_in,
                              void* d_out, int out_size) {
    const float* hidden = (const float*)d_in[0];
    const float* mask   = (const float*)d_in[1];
    const float* w_qkv  = (const float*)d_in[2];
    const float* b_qkv  = (const float*)d_in[3];
    const float* w_out  = (const float*)d_in[4];
    const float* b_out  = (const float*)d_in[5];
    const float* ln_g   = (const float*)d_in[6];
    const float* ln_b   = (const float*)d_in[7];
    float* out = (float*)d_out;

    float *xln, *qkv, *attn;
    cudaGetSymbolAddress((void**)&xln,  g_xln);
    cudaGetSymbolAddress((void**)&qkv,  g_qkv);
    cudaGetSymbolAddress((void**)&attn, g_attn);

    // 1) LayerNorm
    ln_kernel<<<MROWS, 256>>>(hidden, ln_g, ln_b, xln);

    // 2) QKV projection (+bias, K pre-scale by 1/8)
    dim3 g1(N3 / 128, MROWS / 128);
    mm_tf32<0><<<g1, 256>>>(xln, w_qkv, b_qkv, nullptr, qkv, N3);

    // 3) Flash attention (tf32 tensor cores)
    cudaFuncSetAttribute(attn_tf32,
                         cudaFuncAttributeMaxDynamicSharedMemorySize, ATTN_SMEM);
    dim3 g2(SEQ / QT, NHEAD, BATCH);
    attn_tf32<<<g2, 128, ATTN_SMEM>>>(qkv, mask, attn);

    // 4) Output projection + bias + residual
    dim3 g3(HID / 128, MROWS / 128);
    mm_tf32<1><<<g3, 256>>>(attn, w_out, b_out, hidden, out, HID);
}